// round 1
// baseline (speedup 1.0000x reference)
#include <cuda_runtime.h>
#include <math.h>

// Problem constants (fixed-shape problem: N=16384, D=8, pid<2000, K=128, R=1)
#define NMAX    16384
#define NPIDMAX 2048
#define KSEL    128
#define CPT     4       // condensation points per repulsion block
#define CAP     1024    // boundary-bin candidate list capacity per CP
#define RT      256     // threads per repulsion block

// -------- device scratch (allocation-free: __device__ globals) --------
__device__ unsigned long long g_best[NPIDMAX];  // per-pid packed (beta_bits<<32 | ~idx)
__device__ float  g_q[NMAX];
__device__ int    g_cplist[NPIDMAX];
__device__ int    g_cpcount;
__device__ double g_att;
__device__ double g_rep;
__device__ int    g_maskcnt;

__global__ void k_init() {
    int i = blockIdx.x * blockDim.x + threadIdx.x;
    if (i < NPIDMAX) g_best[i] = 0ULL;
    if (i == 0) { g_cpcount = 0; g_att = 0.0; g_rep = 0.0; g_maskcnt = 0; }
}

// q = arctanh(beta)^2 + 0.01 ; per-pid best (max beta, tie -> smallest index)
__global__ void k_bestq(const float* __restrict__ beta, const int* __restrict__ pid, int N) {
    int i = blockIdx.x * blockDim.x + threadIdx.x;
    if (i >= N) return;
    float b = beta[i];
    float t = atanhf(b);
    g_q[i] = t * t + 0.01f;
    int p = pid[i];
    if (p > 0 && p < NPIDMAX) {
        unsigned long long key =
            ((unsigned long long)__float_as_uint(b) << 32) |
            (unsigned long long)(0xFFFFFFFFu - (unsigned)i);
        atomicMax(&g_best[p], key);
    }
}

__global__ void k_compact() {
    int p = blockIdx.x * blockDim.x + threadIdx.x;
    if (p <= 0 || p >= NPIDMAX) return;
    unsigned long long key = g_best[p];
    if (key != 0ULL) {
        int idx = (int)(0xFFFFFFFFu - (unsigned)(key & 0xFFFFFFFFull));
        int pos = atomicAdd(&g_cpcount, 1);
        g_cplist[pos] = idx;
    }
}

// attraction: sum over masked hits of ||x_i - x_alpha||^2 * q_i * q_alpha
__global__ void k_attract(const float* __restrict__ x, const int* __restrict__ pid,
                          const int* __restrict__ recon, const float* __restrict__ pt,
                          const float* __restrict__ eta, int N) {
    int i = blockIdx.x * blockDim.x + threadIdx.x;
    float va = 0.0f; int m = 0;
    if (i < N) {
        int p = pid[i];
        if (p > 0 && pt[i] > 0.9f && recon[i] > 0 && fabsf(eta[i]) < 4.0f) {
            unsigned long long key = g_best[p];
            int a = (int)(0xFFFFFFFFu - (unsigned)(key & 0xFFFFFFFFull));
            const float4* xi = (const float4*)(x + (size_t)i * 8);
            const float4* xa = (const float4*)(x + (size_t)a * 8);
            float4 i0 = xi[0], i1 = xi[1], a0 = xa[0], a1 = xa[1];
            float d, d2 = 0.0f;
            d = i0.x - a0.x; d2 += d * d;
            d = i0.y - a0.y; d2 += d * d;
            d = i0.z - a0.z; d2 += d * d;
            d = i0.w - a0.w; d2 += d * d;
            d = i1.x - a1.x; d2 += d * d;
            d = i1.y - a1.y; d2 += d * d;
            d = i1.z - a1.z; d2 += d * d;
            d = i1.w - a1.w; d2 += d * d;
            va = d2 * g_q[i] * g_q[a];
            m = 1;
        }
    }
    #pragma unroll
    for (int o = 16; o; o >>= 1) {
        va += __shfl_down_sync(0xFFFFFFFFu, va, o);
        m  += __shfl_down_sync(0xFFFFFFFFu, m,  o);
    }
    if ((threadIdx.x & 31) == 0 && (m || va != 0.0f)) {
        atomicAdd(&g_att, (double)va);
        atomicAdd(&g_maskcnt, m);
    }
}

// repulsion: per condensation point, exact 128-nearest within R=1, sum (1-sqrt(d2))*q_c*q_j
// over selected neighbors with different pid.
__global__ void __launch_bounds__(RT) k_repulse(const float* __restrict__ x,
                                                const int* __restrict__ pid, int N) {
    __shared__ float s_xc[CPT][8];
    __shared__ float s_qc[CPT];
    __shared__ int   s_pidc[CPT];
    __shared__ int   s_cidx[CPT];
    __shared__ unsigned int s_hist[CPT][256];
    __shared__ int   s_B[CPT];
    __shared__ int   s_r[CPT];
    __shared__ int   s_lcnt[CPT];
    __shared__ float s_sum[CPT];
    __shared__ float s_ld2[CPT][CAP];
    __shared__ float s_lw[CPT][CAP];

    int tid  = threadIdx.x;
    int ncp  = g_cpcount;
    int cbase = blockIdx.x * CPT;
    if (cbase >= ncp) return;
    int nact = min(CPT, ncp - cbase);

    if (tid < CPT) { s_lcnt[tid] = 0; s_sum[tid] = 0.0f; }
    for (int h = tid; h < CPT * 256; h += RT) ((unsigned int*)s_hist)[h] = 0u;
    if (tid < nact) {
        int c = g_cplist[cbase + tid];
        s_cidx[tid] = c;
        s_qc[tid]   = g_q[c];
        s_pidc[tid] = pid[c];
        #pragma unroll
        for (int d = 0; d < 8; d++) s_xc[tid][d] = x[(size_t)c * 8 + d];
    }
    __syncthreads();

    // ---- Pass A: histogram of d2 in [0,1] (256 bins) over all nodes, per CP ----
    for (int j = tid; j < N; j += RT) {
        float4 v0 = *(const float4*)(x + (size_t)j * 8);
        float4 v1 = *(const float4*)(x + (size_t)j * 8 + 4);
        #pragma unroll
        for (int c = 0; c < CPT; c++) {
            if (c < nact) {
                float d, d2 = 0.0f;
                d = v0.x - s_xc[c][0]; d2 += d * d;
                d = v0.y - s_xc[c][1]; d2 += d * d;
                d = v0.z - s_xc[c][2]; d2 += d * d;
                d = v0.w - s_xc[c][3]; d2 += d * d;
                d = v1.x - s_xc[c][4]; d2 += d * d;
                d = v1.y - s_xc[c][5]; d2 += d * d;
                d = v1.z - s_xc[c][6]; d2 += d * d;
                d = v1.w - s_xc[c][7]; d2 += d * d;
                if (d2 <= 1.0f && j != s_cidx[c]) {
                    int bin = (int)(d2 * 256.0f); bin = min(bin, 255);
                    atomicAdd(&s_hist[c][bin], 1u);
                }
            }
        }
    }
    __syncthreads();

    // ---- Find boundary bin B (contains the 128th-smallest d2) and residual r ----
    if (tid < nact) {
        int cum = 0, B = 256, r = 0;
        for (int b = 0; b < 256; b++) {
            int nc = cum + (int)s_hist[tid][b];
            if (nc > KSEL) { B = b; r = KSEL - cum; break; }
            cum = nc;
        }
        s_B[tid] = B; s_r[tid] = r;
    }
    __syncthreads();

    // ---- Pass B: accumulate bins < B fully; gather boundary-bin candidates ----
    float loc[CPT];
    #pragma unroll
    for (int c = 0; c < CPT; c++) loc[c] = 0.0f;

    for (int j = tid; j < N; j += RT) {
        float4 v0 = *(const float4*)(x + (size_t)j * 8);
        float4 v1 = *(const float4*)(x + (size_t)j * 8 + 4);
        int   pj = pid[j];
        float qj = g_q[j];
        #pragma unroll
        for (int c = 0; c < CPT; c++) {
            if (c < nact) {
                float d, d2 = 0.0f;
                d = v0.x - s_xc[c][0]; d2 += d * d;
                d = v0.y - s_xc[c][1]; d2 += d * d;
                d = v0.z - s_xc[c][2]; d2 += d * d;
                d = v0.w - s_xc[c][3]; d2 += d * d;
                d = v1.x - s_xc[c][4]; d2 += d * d;
                d = v1.y - s_xc[c][5]; d2 += d * d;
                d = v1.z - s_xc[c][6]; d2 += d * d;
                d = v1.w - s_xc[c][7]; d2 += d * d;
                if (d2 <= 1.0f && j != s_cidx[c]) {
                    int bin = (int)(d2 * 256.0f); bin = min(bin, 255);
                    int B = s_B[c];
                    if (bin < B) {
                        if (pj != s_pidc[c]) loc[c] += (1.0f - sqrtf(d2)) * qj;
                    } else if (bin == B) {
                        int pos = atomicAdd(&s_lcnt[c], 1);
                        if (pos < CAP) {
                            s_ld2[c][pos] = d2;
                            s_lw[c][pos]  = (pj != s_pidc[c]) ? (1.0f - sqrtf(d2)) * qj : 0.0f;
                        }
                    }
                }
            }
        }
    }
    // reduce per-thread accumulators
    #pragma unroll
    for (int c = 0; c < CPT; c++) {
        float v = loc[c];
        #pragma unroll
        for (int o = 16; o; o >>= 1) v += __shfl_down_sync(0xFFFFFFFFu, v, o);
        if ((tid & 31) == 0 && c < nact) atomicAdd(&s_sum[c], v);
    }
    __syncthreads();

    // ---- Boundary bin: exact rank-select the r smallest, add their weights ----
    for (int c = 0; c < nact; c++) {
        int m = min(s_lcnt[c], CAP);
        int r = s_r[c];
        float part = 0.0f;
        if (r > 0) {
            for (int e = tid; e < m; e += RT) {
                float de = s_ld2[c][e];
                int rank = 0;
                for (int k = 0; k < m; k++) {
                    float dk = s_ld2[c][k];
                    rank += (dk < de) || (dk == de && k < e);
                }
                if (rank < r) part += s_lw[c][e];
            }
        }
        #pragma unroll
        for (int o = 16; o; o >>= 1) part += __shfl_down_sync(0xFFFFFFFFu, part, o);
        if ((tid & 31) == 0) atomicAdd(&s_sum[c], part);
    }
    __syncthreads();

    if (tid < nact) {
        atomicAdd(&g_rep, (double)(s_sum[tid] * s_qc[tid]));
    }
}

__global__ void k_final(float* out, int N) {
    if (blockIdx.x == 0 && threadIdx.x == 0) {
        int mc = g_maskcnt;
        out[0] = (float)(mc > 0 ? g_att / (double)mc : 0.0);
        out[1] = (float)(g_rep / (double)N);
        out[2] = 0.0f;
        out[3] = 0.0f;
    }
}

extern "C" void kernel_launch(void* const* d_in, const int* in_sizes, int n_in,
                              void* d_out, int out_size) {
    const float* beta  = (const float*)d_in[0];
    const float* x     = (const float*)d_in[1];
    const int*   pid   = (const int*)d_in[2];
    const int*   recon = (const int*)d_in[3];
    const float* pt    = (const float*)d_in[4];
    const float* eta   = (const float*)d_in[5];
    float* out = (float*)d_out;
    int N = in_sizes[0];

    k_init<<<(NPIDMAX + 255) / 256, 256>>>();
    k_bestq<<<(N + 255) / 256, 256>>>(beta, pid, N);
    k_compact<<<(NPIDMAX + 255) / 256, 256>>>();
    k_attract<<<(N + 255) / 256, 256>>>(x, pid, recon, pt, eta, N);
    int nrb = (NPIDMAX + CPT - 1) / CPT;  // 512 blocks; inactive ones exit on g_cpcount
    k_repulse<<<nrb, RT>>>(x, pid, N);
    k_final<<<1, 32>>>(out, N);
}